// round 1
// baseline (speedup 1.0000x reference)
#include <cuda_runtime.h>

#define NUM_RBF 64
#define CUTOFF  5.0f
#define MAX_G   64
#define NCTAS   1184
#define BLOCK   256

// Scratch (no allocations allowed): packed node data, fused weight table, per-CTA partials.
__device__ __align__(16) float4 g_pos4[131072];            // {x,y,z, bits(type | batch<<5)}
__device__ __align__(16) float  g_w[262144];               // rbf_params * radial_filters
__device__ float g_part[NCTAS * MAX_G];

__global__ void prep_kernel(const float* __restrict__ pos,
                            const float* __restrict__ rbf,
                            const float* __restrict__ filt,
                            const int*   __restrict__ types,
                            const int*   __restrict__ batch,
                            int N, int WN) {
    int i = blockIdx.x * blockDim.x + threadIdx.x;
    if (i < N) {
        float4 p;
        p.x = pos[3 * i + 0];
        p.y = pos[3 * i + 1];
        p.z = pos[3 * i + 2];
        int bits = (types[i] & 31) | ((batch[i] & 63) << 5);
        p.w = __int_as_float(bits);
        g_pos4[i] = p;
    }
    if (i < WN) g_w[i] = rbf[i] * filt[i];
}

__global__ void __launch_bounds__(BLOCK) edge_kernel(const int* __restrict__ ei,
                                                     int E, int T) {
    __shared__ float esm[MAX_G];
    if (threadIdx.x < MAX_G) esm[threadIdx.x] = 0.0f;
    __syncthreads();

    const float DELTA     = CUTOFF / (NUM_RBF - 1);          // linspace spacing = 5/63
    const float INV_DELTA = (NUM_RBF - 1) / CUTOFF;
    const float GAMMA     = (NUM_RBF / CUTOFF) * (NUM_RBF / CUTOFF);  // 163.84
    const float PI_OVER_C = 3.14159265358979f / CUTOFF;

    int stride = gridDim.x * blockDim.x;
    for (int e = blockIdx.x * blockDim.x + threadIdx.x; e < E; e += stride) {
        int src = ei[e];
        int dst = ei[e + E];
        float4 a = g_pos4[src];
        float4 b = g_pos4[dst];
        float dx = b.x - a.x, dy = b.y - a.y, dz = b.z - a.z;
        float d = sqrtf(dx * dx + dy * dy + dz * dz + 1e-12f);

        if (d < CUTOFF) {   // fc == 0 otherwise -> zero contribution, skip everything
            int ab = __float_as_int(a.w);
            int bb = __float_as_int(b.w);
            int ta = ab & 31, tb = bb & 31;
            int g  = (ab >> 5) & 63;                 // batch[src]
            int lo = min(ta, tb), hi = max(ta, tb);
            const float4* wrow =
                reinterpret_cast<const float4*>(g_w + (lo * T + hi) * NUM_RBF);

            // Only mus within ~5 spacings of d matter: exp(-163.84 * (5*Delta)^2) ~ 6e-12.
            float t  = d * INV_DELTA;
            int   m0 = (int)fmaxf(0.0f, ceilf(t - 5.0f));
            int   m1 = (int)fminf(63.0f, t + 5.0f);
            int   q0 = m0 >> 2, q1 = m1 >> 2;        // aligned float4 quads

            float acc = 0.0f;
            float x0 = d - (float)(q0 * 4) * DELTA;
            for (int q = q0; q <= q1; ++q) {
                float4 wv = __ldg(wrow + q);
                float x1 = x0 - DELTA;
                float x2 = x1 - DELTA;
                float x3 = x2 - DELTA;
                acc += wv.x * __expf(-GAMMA * x0 * x0)
                     + wv.y * __expf(-GAMMA * x1 * x1)
                     + wv.z * __expf(-GAMMA * x2 * x2)
                     + wv.w * __expf(-GAMMA * x3 * x3);
                x0 = x3 - DELTA;
            }
            float fc = 0.5f * (__cosf(PI_OVER_C * d) + 1.0f);
            atomicAdd(&esm[g], acc * fc);
        }
    }

    __syncthreads();
    if (threadIdx.x < MAX_G)
        g_part[blockIdx.x * MAX_G + threadIdx.x] = esm[threadIdx.x];
}

__global__ void reduce_kernel(float* __restrict__ out, int G) {
    __shared__ float s[512];
    int tid   = threadIdx.x;
    int g     = tid & 63;
    int slice = tid >> 6;          // 8 slices
    float sum = 0.0f;
    for (int c = slice; c < NCTAS; c += 8)
        sum += g_part[c * MAX_G + g];
    s[tid] = sum;
    __syncthreads();
    if (slice == 0) {
        float tot = sum;
        #pragma unroll
        for (int ss = 1; ss < 8; ++ss) tot += s[ss * 64 + g];
        if (g < G) out[g] = tot;
    }
}

extern "C" void kernel_launch(void* const* d_in, const int* in_sizes, int n_in,
                              void* d_out, int out_size) {
    const float* pos   = (const float*)d_in[0];
    const float* rbf   = (const float*)d_in[1];
    const float* filt  = (const float*)d_in[2];
    const int*   ei    = (const int*)d_in[3];
    const int*   types = (const int*)d_in[4];
    const int*   batch = (const int*)d_in[5];

    int N  = in_sizes[0] / 3;
    int WN = in_sizes[1];
    int E  = in_sizes[3] / 2;
    int G  = out_size < MAX_G ? out_size : MAX_G;

    int T = 1;
    while (T * T * NUM_RBF < WN) T++;   // WN = T*T*64 -> T (25 here)

    int prep_n = (N > WN) ? N : WN;
    int prep_blocks = (prep_n + 255) / 256;

    prep_kernel<<<prep_blocks, 256>>>(pos, rbf, filt, types, batch, N, WN);
    edge_kernel<<<NCTAS, BLOCK>>>(ei, E, T);
    reduce_kernel<<<1, 512>>>((float*)d_out, G);
}

// round 2
// speedup vs baseline: 1.2431x; 1.2431x over previous
#include <cuda_runtime.h>

#define NUM_RBF 64
#define CUTOFF  5.0f
#define MAX_G   64
#define BLOCK   512
#define NCTAS   148
#define WSTRIDE 68          // 64 + 4 pad floats -> bank-group = (row+quad) mod 8

// Packed node data: {x,y,z, bits(type | batch<<5)}. No other gmem scratch needed.
__device__ __align__(16) float4 g_pos4[65536];

__global__ void prep_kernel(const float* __restrict__ pos,
                            const int*   __restrict__ types,
                            const int*   __restrict__ batch,
                            float*       __restrict__ out,
                            int N, int G) {
    int i = blockIdx.x * blockDim.x + threadIdx.x;
    if (i < G) out[i] = 0.0f;               // d_out is poisoned; zero it here
    if (i < N) {
        float4 p;
        p.x = pos[3 * i + 0];
        p.y = pos[3 * i + 1];
        p.z = pos[3 * i + 2];
        p.w = __int_as_float((types[i] & 31) | ((batch[i] & 63) << 5));
        g_pos4[i] = p;
    }
}

extern __shared__ float s_dyn[];

__device__ __forceinline__ void edge_compute(float4 a, float4 b, int T,
                                             const float* __restrict__ sw,
                                             float* __restrict__ esm) {
    const float DELTA     = CUTOFF / (NUM_RBF - 1);
    const float INV_DELTA = (NUM_RBF - 1) / CUTOFF;
    const float GAMMA     = (NUM_RBF / CUTOFF) * (NUM_RBF / CUTOFF);
    const float PI_OVER_C = 3.14159265358979f / CUTOFF;

    float dx = b.x - a.x, dy = b.y - a.y, dz = b.z - a.z;
    float d = sqrtf(dx * dx + dy * dy + dz * dz + 1e-12f);
    if (d < CUTOFF) {
        int ab = __float_as_int(a.w);
        int bb = __float_as_int(b.w);
        int ta = ab & 31, tb = bb & 31;
        int g  = (ab >> 5) & 63;
        int lo = min(ta, tb), hi = max(ta, tb);
        int base = (lo * T + hi) * WSTRIDE;

        float t  = d * INV_DELTA;
        int   m0 = max(0, (int)ceilf(t - 4.0f));
        int   m1 = min(NUM_RBF - 1, (int)(t + 4.0f));
        int   q0 = m0 >> 2, q1 = m1 >> 2;          // <= 3 aligned quads

        float acc = 0.0f;
        float x0  = d - (float)(q0 * 4) * DELTA;
        for (int q = q0; q <= q1; ++q) {
            float4 wv = *(const float4*)&sw[base + q * 4];
            float x1 = x0 - DELTA;
            float x2 = x1 - DELTA;
            float x3 = x2 - DELTA;
            acc = fmaf(wv.x, __expf(-GAMMA * x0 * x0), acc);
            acc = fmaf(wv.y, __expf(-GAMMA * x1 * x1), acc);
            acc = fmaf(wv.z, __expf(-GAMMA * x2 * x2), acc);
            acc = fmaf(wv.w, __expf(-GAMMA * x3 * x3), acc);
            x0 = x3 - DELTA;
        }
        float fc = 0.5f * (__cosf(PI_OVER_C * d) + 1.0f);
        atomicAdd(&esm[g], acc * fc);
    }
}

__global__ void __launch_bounds__(BLOCK, 1) edge_kernel(
        const int*   __restrict__ ei,
        const float* __restrict__ rbf,
        const float* __restrict__ filt,
        float*       __restrict__ out,
        int E, int T) {
    const int rows = T * T;
    float* sw  = s_dyn;                   // rows * WSTRIDE floats, padded
    float* esm = s_dyn + rows * WSTRIDE;  // 64 graph bins
    int tid = threadIdx.x;

    // Build fused weight table (rbf * filt) directly in smem, padded stride.
    int nq = rows * (NUM_RBF / 4);
    for (int idx = tid; idx < nq; idx += BLOCK) {
        int r = idx >> 4, q = idx & 15;
        float4 va = __ldg((const float4*)rbf + idx);
        float4 vb = __ldg((const float4*)filt + idx);
        float4 w;
        w.x = va.x * vb.x; w.y = va.y * vb.y;
        w.z = va.z * vb.z; w.w = va.w * vb.w;
        *(float4*)&sw[r * WSTRIDE + q * 4] = w;
    }
    if (tid < MAX_G) esm[tid] = 0.0f;
    __syncthreads();

    if ((E & 3) == 0) {
        int nquad = E >> 2;
        const int4* s4p = (const int4*)ei;
        const int4* d4p = (const int4*)(ei + E);
        for (int i = blockIdx.x * BLOCK + tid; i < nquad; i += NCTAS * BLOCK) {
            int4 s4 = __ldg(s4p + i);
            int4 d4 = __ldg(d4p + i);
            // Issue all 8 gathers up front for MLP.
            float4 a0 = __ldg(&g_pos4[s4.x]);
            float4 b0 = __ldg(&g_pos4[d4.x]);
            float4 a1 = __ldg(&g_pos4[s4.y]);
            float4 b1 = __ldg(&g_pos4[d4.y]);
            float4 a2 = __ldg(&g_pos4[s4.z]);
            float4 b2 = __ldg(&g_pos4[d4.z]);
            float4 a3 = __ldg(&g_pos4[s4.w]);
            float4 b3 = __ldg(&g_pos4[d4.w]);
            edge_compute(a0, b0, T, sw, esm);
            edge_compute(a1, b1, T, sw, esm);
            edge_compute(a2, b2, T, sw, esm);
            edge_compute(a3, b3, T, sw, esm);
        }
    } else {
        for (int e = blockIdx.x * BLOCK + tid; e < E; e += NCTAS * BLOCK) {
            int src = __ldg(ei + e);
            int dst = __ldg(ei + e + E);
            float4 a = __ldg(&g_pos4[src]);
            float4 b = __ldg(&g_pos4[dst]);
            edge_compute(a, b, T, sw, esm);
        }
    }

    __syncthreads();
    if (tid < MAX_G) atomicAdd(&out[tid], esm[tid]);
}

extern "C" void kernel_launch(void* const* d_in, const int* in_sizes, int n_in,
                              void* d_out, int out_size) {
    const float* pos   = (const float*)d_in[0];
    const float* rbf   = (const float*)d_in[1];
    const float* filt  = (const float*)d_in[2];
    const int*   ei    = (const int*)d_in[3];
    const int*   types = (const int*)d_in[4];
    const int*   batch = (const int*)d_in[5];

    int N  = in_sizes[0] / 3;
    int WN = in_sizes[1];
    int E  = in_sizes[3] / 2;
    int G  = out_size < MAX_G ? out_size : MAX_G;

    int T = 1;
    while (T * T * NUM_RBF < WN) T++;      // 25 for this dataset

    int smem_bytes = T * T * WSTRIDE * 4 + MAX_G * 4;
    cudaFuncSetAttribute(edge_kernel,
                         cudaFuncAttributeMaxDynamicSharedMemorySize, smem_bytes);

    int prep_blocks = (N + 255) / 256;
    prep_kernel<<<prep_blocks, 256>>>(pos, types, batch, (float*)d_out, N, G);
    edge_kernel<<<NCTAS, BLOCK, smem_bytes>>>(ei, rbf, filt, (float*)d_out, E, T);
}